// round 3
// baseline (speedup 1.0000x reference)
#include <cuda_runtime.h>

// x: (B=16, C=256, L=16384) fp32, kernel=4, stride=4 -> out (B, 256, 4096) fp32
// c_curv = 1.0, eps = 1e-7
#define C_CH    256
#define L_IN    16384
#define OUT_LEN 4096
#define EPS_F   1e-7f

// Block: 128 threads = 4 warps, covering 4 output columns x all 256 channels.
// Thread t: column j = t&3, channel group cg = t>>2 (0..31), channels cg+32i.
// Warp layout: lane = j + 4*cgl, cgl = lane>>2 in 0..7; warp w holds channel
// groups cg = 8w..8w+7. One float4 load per channel = 8 LDG.128 per thread;
// each warp load instruction touches 8 channel rows x 64 contiguous bytes.
//
// Cross-channel reduction of the 4x4 window Gram matrix (10 sums):
//   warp shuffle over cgl (xor 4,8,16), then ONE smem stage where 4 threads
//   (one per column) sum the 4 warp partials and do the scalar math.
// Only 2 __syncthreads total.
__global__ __launch_bounds__(128) void hpool_kernel(
    const float* __restrict__ x, float* __restrict__ out)
{
    const int t    = threadIdx.x;
    const int j    = t & 3;
    const int cg   = t >> 2;       // 0..31
    const int lane = t & 31;
    const int warp = t >> 5;       // 0..3
    const int l0   = blockIdx.x * 4;
    const int b    = blockIdx.y;

    // ---- load window: 8 channels x 4 positions, one float4 each ----
    const size_t base_in = (size_t)b * (C_CH * L_IN) + (size_t)(l0 + j) * 4;
    float4 w[8];
#pragma unroll
    for (int i = 0; i < 8; i++) {
        w[i] = *reinterpret_cast<const float4*>(x + base_in + (size_t)(cg + 32 * i) * L_IN);
    }

    // ---- Gram partials: q0..3 = diag; q4..9 = (0,1)(0,2)(0,3)(1,2)(1,3)(2,3) ----
    float s[10];
#pragma unroll
    for (int q = 0; q < 10; q++) s[q] = 0.f;
#pragma unroll
    for (int i = 0; i < 8; i++) {
        const float a0 = w[i].x, a1 = w[i].y, a2 = w[i].z, a3 = w[i].w;
        s[0] += a0 * a0; s[1] += a1 * a1; s[2] += a2 * a2; s[3] += a3 * a3;
        s[4] += a0 * a1; s[5] += a0 * a2; s[6] += a0 * a3;
        s[7] += a1 * a2; s[8] += a1 * a3; s[9] += a2 * a3;
    }
    // reduce across the 8 channel-group lanes sharing column j in this warp
#pragma unroll
    for (int q = 0; q < 10; q++) {
        s[q] += __shfl_xor_sync(0xffffffffu, s[q], 4);
        s[q] += __shfl_xor_sync(0xffffffffu, s[q], 8);
        s[q] += __shfl_xor_sync(0xffffffffu, s[q], 16);
    }

    __shared__ float red[4][4][10];   // [warp][col][q]
    __shared__ float cf[4][4];        // [col][p] fused coefficients
    if (lane < 4) {
#pragma unroll
        for (int q = 0; q < 10; q++) red[warp][lane][q] = s[q];
    }
    __syncthreads();

    // fused cross-warp sum + per-column scalar math (one thread per column)
    if (t < 4) {
        float G[10];
#pragma unroll
        for (int q = 0; q < 10; q++)
            G[q] = red[0][t][q] + red[1][t][q] + red[2][t][q] + red[3][t][q];

        float f[4], gam[4], denom = 0.f;
#pragma unroll
        for (int p = 0; p < 4; p++) {
            const float x2 = G[p];
            f[p] = 2.0f / (1.0f + x2);
            gam[p] = rsqrtf(fmaxf(1.0f - f[p] * f[p] * x2, EPS_F));
            denom += gam[p];
        }
        const float inv_d = 1.0f / denom;
        const float c0 = gam[0] * f[0] * inv_d;
        const float c1 = gam[1] * f[1] * inv_d;
        const float c2 = gam[2] * f[2] * inv_d;
        const float c3 = gam[3] * f[3] * inv_d;

        const float mk2 =
            c0 * c0 * G[0] + c1 * c1 * G[1] + c2 * c2 * G[2] + c3 * c3 * G[3] +
            2.0f * (c0 * c1 * G[4] + c0 * c2 * G[5] + c0 * c3 * G[6] +
                    c1 * c2 * G[7] + c1 * c3 * G[8] + c2 * c3 * G[9]);

        const float sc = 1.0f / (1.0f + sqrtf(fmaxf(1.0f - mk2, EPS_F)));
        cf[t][0] = c0 * sc;
        cf[t][1] = c1 * sc;
        cf[t][2] = c2 * sc;
        cf[t][3] = c3 * sc;
    }
    __syncthreads();

    // ---- fused epilogue: out = sum_p cf[j][p] * w[:,p] ----
    const float c0 = cf[j][0], c1 = cf[j][1], c2 = cf[j][2], c3 = cf[j][3];
    const size_t base_out = (size_t)b * (C_CH * OUT_LEN) + (size_t)(l0 + j);
#pragma unroll
    for (int i = 0; i < 8; i++) {
        out[base_out + (size_t)(cg + 32 * i) * OUT_LEN] =
            c0 * w[i].x + c1 * w[i].y + c2 * w[i].z + c3 * w[i].w;
    }
}

extern "C" void kernel_launch(void* const* d_in, const int* in_sizes, int n_in,
                              void* d_out, int out_size)
{
    const float* x = (const float*)d_in[0];
    float* out = (float*)d_out;

    const int B = in_sizes[0] / (C_CH * L_IN);   // 16
    dim3 grid(OUT_LEN / 4, B);                   // (1024, 16)
    hpool_kernel<<<grid, 128>>>(x, out);
}

// round 4
// speedup vs baseline: 1.0474x; 1.0474x over previous
#include <cuda_runtime.h>

// x: (B=16, C=256, L=16384) fp32, kernel=4, stride=4 -> out (B, 256, 4096) fp32
// c_curv = 1.0, eps = 1e-7
#define C_CH    256
#define L_IN    16384
#define OUT_LEN 4096
#define EPS_F   1e-7f

// Block: 256 threads = 8 warps, 8 output columns x 256 channels (R2 layout:
// 128B contiguous read runs, full 32B write sectors per channel row).
// Thread t: column j = t&7, channel group cg = t>>3, channels cg+32i (i<8).
//
// Reduction: 4x4 window Gram matrix (10 sums, padded to 12 for vec4 smem).
//   in-warp: shfl_xor 8,16  ->  lanes 0..7 hold per-warp partial for col=lane
//   ONE __syncthreads, then EVERY thread sums the 8 warp partials from smem
//   (24 LDS.128, conflict-free: j*12 mod 32 covers disjoint bank quads) and
//   redundantly computes the per-column coefficients. No serialized stages.
__global__ __launch_bounds__(256) void hpool_kernel(
    const float* __restrict__ x, float* __restrict__ out)
{
    const int t    = threadIdx.x;
    const int j    = t & 7;
    const int lane = t & 31;
    const int warp = t >> 5;
    const int cg   = t >> 3;       // 0..31
    const int l0   = blockIdx.x * 8;
    const int b    = blockIdx.y;

    // ---- load window: 8 channels x 4 positions, one float4 each ----
    const size_t base_in = (size_t)b * (C_CH * L_IN) + (size_t)(l0 + j) * 4;
    float4 w[8];
#pragma unroll
    for (int i = 0; i < 8; i++) {
        const float4* p = reinterpret_cast<const float4*>(
            x + base_in + (size_t)(cg + 32 * i) * L_IN);
        w[i] = __ldcs(p);   // read-once: streaming, don't pollute L2
    }

    // ---- Gram partials: s0..3 diag; s4..9 = (0,1)(0,2)(0,3)(1,2)(1,3)(2,3) ----
    float s[12];
#pragma unroll
    for (int q = 0; q < 12; q++) s[q] = 0.f;
#pragma unroll
    for (int i = 0; i < 8; i++) {
        const float a0 = w[i].x, a1 = w[i].y, a2 = w[i].z, a3 = w[i].w;
        s[0] += a0 * a0; s[1] += a1 * a1; s[2] += a2 * a2; s[3] += a3 * a3;
        s[4] += a0 * a1; s[5] += a0 * a2; s[6] += a0 * a3;
        s[7] += a1 * a2; s[8] += a1 * a3; s[9] += a2 * a3;
    }
    // in-warp reduce across the 4 cgl lanes sharing column j
#pragma unroll
    for (int q = 0; q < 10; q++) {
        s[q] += __shfl_xor_sync(0xffffffffu, s[q], 8);
        s[q] += __shfl_xor_sync(0xffffffffu, s[q], 16);
    }

    __shared__ float4 red[8][8][3];   // [warp][col][vec4 of 12]
    if (lane < 8) {
        red[warp][lane][0] = make_float4(s[0], s[1], s[2], s[3]);
        red[warp][lane][1] = make_float4(s[4], s[5], s[6], s[7]);
        red[warp][lane][2] = make_float4(s[8], s[9], 0.f, 0.f);
    }
    __syncthreads();

    // ---- every thread: cross-warp sum + redundant scalar math ----
    float4 g0 = red[0][j][0], g1 = red[0][j][1], g2 = red[0][j][2];
#pragma unroll
    for (int wq = 1; wq < 8; wq++) {
        const float4 r0 = red[wq][j][0], r1 = red[wq][j][1], r2 = red[wq][j][2];
        g0.x += r0.x; g0.y += r0.y; g0.z += r0.z; g0.w += r0.w;
        g1.x += r1.x; g1.y += r1.y; g1.z += r1.z; g1.w += r1.w;
        g2.x += r2.x; g2.y += r2.y;
    }
    // G: diag = g0.{x,y,z,w}; off = g1.{x,y,z,w}=G01,G02,G03,G12; g2.{x,y}=G13,G23
    float f0 = 2.0f / (1.0f + g0.x);
    float f1 = 2.0f / (1.0f + g0.y);
    float f2 = 2.0f / (1.0f + g0.z);
    float f3 = 2.0f / (1.0f + g0.w);
    const float ga0 = rsqrtf(fmaxf(1.0f - f0 * f0 * g0.x, EPS_F));
    const float ga1 = rsqrtf(fmaxf(1.0f - f1 * f1 * g0.y, EPS_F));
    const float ga2 = rsqrtf(fmaxf(1.0f - f2 * f2 * g0.z, EPS_F));
    const float ga3 = rsqrtf(fmaxf(1.0f - f3 * f3 * g0.w, EPS_F));
    const float inv_d = 1.0f / (ga0 + ga1 + ga2 + ga3);
    float c0 = ga0 * f0 * inv_d;
    float c1 = ga1 * f1 * inv_d;
    float c2 = ga2 * f2 * inv_d;
    float c3 = ga3 * f3 * inv_d;

    const float mk2 =
        c0 * c0 * g0.x + c1 * c1 * g0.y + c2 * c2 * g0.z + c3 * c3 * g0.w +
        2.0f * (c0 * c1 * g1.x + c0 * c2 * g1.y + c0 * c3 * g1.z +
                c1 * c2 * g1.w + c1 * c3 * g2.x + c2 * c3 * g2.y);

    const float sc = 1.0f / (1.0f + sqrtf(fmaxf(1.0f - mk2, EPS_F)));
    c0 *= sc; c1 *= sc; c2 *= sc; c3 *= sc;

    // ---- fused epilogue: out = sum_p c_p * w[:,p] (streaming stores) ----
    const size_t base_out = (size_t)b * (C_CH * OUT_LEN) + (size_t)(l0 + j);
#pragma unroll
    for (int i = 0; i < 8; i++) {
        __stcs(out + base_out + (size_t)(cg + 32 * i) * OUT_LEN,
               c0 * w[i].x + c1 * w[i].y + c2 * w[i].z + c3 * w[i].w);
    }
}

extern "C" void kernel_launch(void* const* d_in, const int* in_sizes, int n_in,
                              void* d_out, int out_size)
{
    const float* x = (const float*)d_in[0];
    float* out = (float*)d_out;

    const int B = in_sizes[0] / (C_CH * L_IN);   // 16
    dim3 grid(OUT_LEN / 8, B);                   // (512, 16)
    hpool_kernel<<<grid, 256>>>(x, out);
}